// round 8
// baseline (speedup 1.0000x reference)
#include <cuda_runtime.h>

#define IMG 28
#define PIX 784            // 28*28
#define B_IMGS 65536
#define CENTER 14

__global__ __launch_bounds__(256)
void sr_row_kernel(const float* __restrict__ x,
                   const int* __restrict__ t,
                   const float* __restrict__ Wk,
                   const float* __restrict__ bias,
                   float* __restrict__ out)
{
    // one thread per image row: idx in [0, 65536*28)
    unsigned idx = blockIdx.x * blockDim.x + threadIdx.x;
    unsigned img = idx / IMG;                 // const-div by 28 -> mulhi
    unsigned row = idx - img * IMG;

    const float* ximg = x + (size_t)img * PIX;
    const float* xrow = ximg + row * IMG;     // row*112B -> 16B aligned

    // load whole row (7 x float4, back-to-back for MLP)
    float v[IMG];
#pragma unroll
    for (int q = 0; q < 7; q++)
        *reinterpret_cast<float4*>(v + 4 * q) =
            *reinterpret_cast<const float4*>(xrow + 4 * q);

    int tv = __ldg(t + img);                              // 0..19
    int r2max = tv * tv;                                  // d2 <= t^2
    int r2min = (tv >= 1) ? (tv - 1) * (tv - 1) : -1;     // d2 <= (t-1)^2

    int dr = (int)row - CENTER;
    int dr2 = dr * dr;

    if (dr2 <= r2max) {
        // ring pixels in this row: (c-14)^2 in (lo, hi]
        int hi = r2max - dr2;
        int lo = r2min - dr2;

        float w[9];
#pragma unroll
        for (int i = 0; i < 9; i++) w[i] = __ldg(Wk + i);
        float bb = __ldg(bias);

#pragma unroll
        for (int c = 0; c < IMG; c++) {
            const int C = (c - CENTER) * (c - CENTER);    // compile-time literal
            if (C <= hi && C > lo) {
                // 3x3 SAME conv at (row, c) on original x
                float acc = bb;
#pragma unroll
                for (int rr = -1; rr <= 1; rr++) {
                    int r2 = (int)row + rr;
                    if (r2 >= 0 && r2 < IMG) {
#pragma unroll
                        for (int cc = -1; cc <= 1; cc++) {
                            int c2 = c + cc;              // bounds compile-time per c
                            if (c2 >= 0 && c2 < IMG)
                                acc = fmaf(w[(rr + 1) * 3 + (cc + 1)],
                                           ximg[r2 * IMG + c2], acc);
                        }
                    }
                }
                v[c] += acc;   // out = x + x0 on the annulus
            }
        }
    }

    float* orow = out + (size_t)img * PIX + row * IMG;
#pragma unroll
    for (int q = 0; q < 7; q++)
        *reinterpret_cast<float4*>(orow + 4 * q) =
            *reinterpret_cast<const float4*>(v + 4 * q);
}

extern "C" void kernel_launch(void* const* d_in, const int* in_sizes, int n_in,
                              void* d_out, int out_size)
{
    const float* x    = (const float*)d_in[0];   // [65536,1,28,28] f32
    const int*   t    = (const int*)  d_in[1];   // [65536] i32
    const float* Wk   = (const float*)d_in[2];   // [1,1,3,3] f32
    const float* bias = (const float*)d_in[3];   // [1] f32
    float* out = (float*)d_out;

    const int total_rows = B_IMGS * IMG;         // 1,835,008
    const int threads = 256;
    const int blocks = total_rows / threads;     // 7168 (exact)

    sr_row_kernel<<<blocks, threads>>>(x, t, Wk, bias, out);
}

// round 13
// speedup vs baseline: 1.2984x; 1.2984x over previous
#include <cuda_runtime.h>

#define IMG 28
#define PIX 784            // 28*28
#define QUADS 196          // float4 quads per image (7 per row, rows never split)
#define B_IMGS 65536
#define NIMG 4             // images per thread (same quad position)
#define CENTER 14

__global__ __launch_bounds__(256)
void sr_quad4_kernel(const float* __restrict__ x,
                     const int* __restrict__ t,
                     const float* __restrict__ Wk,
                     const float* __restrict__ bias,
                     float* __restrict__ out)
{
    unsigned idx  = blockIdx.x * 256u + threadIdx.x;
    unsigned grp  = idx / QUADS;            // image-group (4 images)
    unsigned quad = idx - grp * QUADS;
    unsigned img0 = grp * NIMG;

    // ---- geometry: computed ONCE, reused for 4 images ----
    unsigned row  = quad / 7u;              // const-mul
    unsigned col0 = (quad - row * 7u) * 4u;
    int dr  = (int)row - CENTER;
    int dr2 = dr * dr;

    int d2[4];
#pragma unroll
    for (int k = 0; k < 4; k++) {
        int dc = (int)col0 + k - CENTER;
        d2[k] = dr2 + dc * dc;
    }
    // cols are consecutive -> min/max at the ends or around center
    int d2min = min(min(d2[0], d2[1]), min(d2[2], d2[3]));
    int d2max = max(d2[0], d2[3]);

    // t-interval such that the ring can touch this quad (SUPERSET is fine;
    // exact per-pixel mask re-checked in the slow path)
    int tlo = (int)sqrtf((float)d2min);         // floor <= ceil -> superset
    int thi = (int)sqrtf((float)d2max) + 1;     // >= ceil      -> superset

    const float* xq = x   + (size_t)img0 * PIX + quad * 4;
    float*       oq = out + (size_t)img0 * PIX + quad * 4;

    // ---- front-batched loads: 4 data quads + 4 t values (MLP=8) ----
    float4 v[NIMG];
    int tv[NIMG];
#pragma unroll
    for (int i = 0; i < NIMG; i++)
        v[i] = *reinterpret_cast<const float4*>(xq + i * PIX);
#pragma unroll
    for (int i = 0; i < NIMG; i++)
        tv[i] = __ldg(t + img0 + i);

#pragma unroll
    for (int i = 0; i < NIMG; i++) {
        if (tv[i] >= tlo && tv[i] <= thi) {     // rare: quad near this image's ring
            int r2max = tv[i] * tv[i];
            int r2min = (tv[i] >= 1) ? (tv[i] - 1) * (tv[i] - 1) : -1;
            const float* ximg = x + (size_t)(img0 + i) * PIX;
            float* vv = reinterpret_cast<float*>(&v[i]);
#pragma unroll
            for (int k = 0; k < 4; k++) {
                if (d2[k] <= r2max && d2[k] > r2min) {   // exact annulus test
                    int c = (int)col0 + k;
                    float acc = __ldg(bias);
#pragma unroll
                    for (int rr = -1; rr <= 1; rr++) {
                        int r2i = (int)row + rr;
                        if (r2i >= 0 && r2i < IMG) {
#pragma unroll
                            for (int cc = -1; cc <= 1; cc++) {
                                int c2 = c + cc;
                                if (c2 >= 0 && c2 < IMG)
                                    acc = fmaf(__ldg(Wk + (rr + 1) * 3 + (cc + 1)),
                                               ximg[r2i * IMG + c2], acc);
                            }
                        }
                    }
                    vv[k] += acc;               // out = x + x0 on the annulus
                }
            }
        }
        *reinterpret_cast<float4*>(oq + i * PIX) = v[i];  // store ASAP, cut liveness
    }
}

extern "C" void kernel_launch(void* const* d_in, const int* in_sizes, int n_in,
                              void* d_out, int out_size)
{
    const float* x    = (const float*)d_in[0];   // [65536,1,28,28] f32
    const int*   t    = (const int*)  d_in[1];   // [65536] i32
    const float* Wk   = (const float*)d_in[2];   // [1,1,3,3] f32
    const float* bias = (const float*)d_in[3];   // [1] f32
    float* out = (float*)d_out;

    const int threads = 256;
    const int total   = (B_IMGS / NIMG) * QUADS; // 16384*196 = 3,211,264
    const int blocks  = total / threads;         // 12544 (exact)

    sr_quad4_kernel<<<blocks, threads>>>(x, t, Wk, bias, out);
}